// round 9
// baseline (speedup 1.0000x reference)
#include <cuda_runtime.h>
#include <math.h>
#include <stdint.h>

#define BB 64
#define TT 512
#define II 1024
#define HH 1024
#define GG 4096              // 4*H
#define MM (BB*TT)           // 32768
#define KSPLIT 4
#define NBLK 256             // persistent kernel grid size
#define NLEAF 16             // barrier tree fan-in (16 leaves x 16 blocks)

// Scratch (device globals: allocation-free per harness rules)
__device__ float g_xproj[(size_t)MM * GG];          // [B*T, 4H]  512 MB
__device__ float g_hbuf [(size_t)MM * HH];          // [B, T, H]  128 MB
__device__ float g_h    [BB * HH];                  // current h
__device__ float g_part [(size_t)KSPLIT * BB * GG]; // split-K partials, 4 MB

// Tree grid barrier state (zero-initialized, monotonic counters)
__device__ unsigned g_leaf[NLEAF * 32];             // 128B-strided leaf counters
__device__ unsigned g_root;
__device__ volatile unsigned g_bar_gen;

__device__ __forceinline__ void grid_barrier()
{
    __syncthreads();
    if (threadIdx.x == 0) {
        unsigned gen = g_bar_gen;
        __threadfence();                                   // release
        unsigned p = atomicAdd(&g_leaf[(blockIdx.x & (NLEAF - 1)) * 32], 1u);
        if ((p & 15u) == 15u) {                            // last of 16 in leaf
            unsigned r = atomicAdd(&g_root, 1u);
            if ((r & 15u) == 15u) {                        // last leaf
                __threadfence();
                g_bar_gen = gen + 1;                       // release all
            }
        }
        while (g_bar_gen == gen) { }                       // spin
        __threadfence();                                   // acquire
    }
    __syncthreads();
}

// ---------------------------------------------------------------------------
// tf32 / cp.async helpers
// ---------------------------------------------------------------------------
__device__ __forceinline__ uint32_t f2tf(float f)
{
    uint32_t u;
    asm("cvt.rna.tf32.f32 %0, %1;" : "=r"(u) : "f"(f));
    return u;
}

__device__ __forceinline__ void mma_tf32(float* d,
    uint32_t a0, uint32_t a1, uint32_t a2, uint32_t a3,
    uint32_t b0, uint32_t b1)
{
    asm("mma.sync.aligned.m16n8k8.row.col.f32.tf32.tf32.f32 "
        "{%0,%1,%2,%3}, {%4,%5,%6,%7}, {%8,%9}, {%0,%1,%2,%3};"
        : "+f"(d[0]), "+f"(d[1]), "+f"(d[2]), "+f"(d[3])
        : "r"(a0), "r"(a1), "r"(a2), "r"(a3), "r"(b0), "r"(b1));
}

__device__ __forceinline__ void cp_async16_ca(uint32_t saddr, const void* g)
{
    asm volatile("cp.async.ca.shared.global [%0], [%1], 16;" :: "r"(saddr), "l"(g));
}
__device__ __forceinline__ void cp_async16_cg(uint32_t saddr, const void* g)
{
    asm volatile("cp.async.cg.shared.global [%0], [%1], 16;" :: "r"(saddr), "l"(g));
}
__device__ __forceinline__ void cp_commit() { asm volatile("cp.async.commit_group;"); }
template<int N>
__device__ __forceinline__ void cp_wait() { asm volatile("cp.async.wait_group %0;" :: "n"(N)); }

// ---------------------------------------------------------------------------
// Input-projection GEMM (tf32 tensor cores, 3-stage cp.async pipeline):
//   xproj[m,n] = sum_k A[m,k]*W[n,k] + bih[n] + bhh[n]
// Tile 128x128, k-chunks of 32, triple-buffered SMEM stride-36 rows,
// ONE __syncthreads per chunk. 8 warps 2(m)x4(n), warp tile 64x32.
// ---------------------------------------------------------------------------
#define KC 32
#define ASTR 36
#define NCHUNK (II / KC)      // 32

__global__ void __launch_bounds__(256, 2) gemm_bias_tc_kernel(
    const float* __restrict__ Ain,
    const float* __restrict__ W,
    const float* __restrict__ bih,
    const float* __restrict__ bhh,
    int in_is_hbuf)
{
    extern __shared__ float smf[];
    float* As = smf;                       // [3][128][36] raw fp32
    float* Bs = smf + 3 * 128 * ASTR;      // [3][128][36]

    const float* A = in_is_hbuf ? (const float*)g_hbuf : Ain;

    const int tid  = threadIdx.x;
    const int bn   = blockIdx.x;             // 0..31
    const int bm   = blockIdx.y;             // 0..255
    const int lane = tid & 31, wid = tid >> 5;
    const int g    = lane >> 2, tg = lane & 3;
    const int wm   = wid >> 2;               // 0..1
    const int wn   = wid & 3;                // 0..3
    const int mW   = wm * 64, nW = wn * 32;

    // staging map: row sm, k-half kh (16 floats per thread per matrix)
    const int sm = tid & 127;
    const int kh = tid >> 7;                 // 0/1

    const float* Ag = A + (size_t)(bm * 128 + sm) * II + 16 * kh;
    const float* Wg = W + (size_t)(bn * 128 + sm) * II + 16 * kh;

    const uint32_t sA = (uint32_t)__cvta_generic_to_shared(As + sm * ASTR + 16 * kh);
    const uint32_t sB = (uint32_t)__cvta_generic_to_shared(Bs + sm * ASTR + 16 * kh);
    const uint32_t bufStride = 128 * ASTR * 4;   // bytes per buffer

    float acc[4][4][4];
    #pragma unroll
    for (int mt = 0; mt < 4; mt++)
        #pragma unroll
        for (int nt = 0; nt < 4; nt++)
            #pragma unroll
            for (int e = 0; e < 4; e++) acc[mt][nt][e] = 0.f;

    float bb[4][2];
    #pragma unroll
    for (int nt = 0; nt < 4; nt++)
        #pragma unroll
        for (int e = 0; e < 2; e++) {
            int n = bn * 128 + nW + nt * 8 + 2 * tg + e;
            bb[nt][e] = bih[n] + bhh[n];
        }

    // prologue: prefetch chunks 0 and 1 into bufs 0,1 (groups 0,1)
    #pragma unroll
    for (int q = 0; q < 4; q++) {
        cp_async16_ca(sA + q * 16, Ag + 4 * q);
        cp_async16_ca(sB + q * 16, Wg + 4 * q);
    }
    cp_commit();
    #pragma unroll
    for (int q = 0; q < 4; q++) {
        cp_async16_ca(sA + bufStride + q * 16, Ag + KC + 4 * q);
        cp_async16_ca(sB + bufStride + q * 16, Wg + KC + 4 * q);
    }
    cp_commit();

    int buf = 0;
    for (int i = 0; i < NCHUNK; i++) {
        if (i == NCHUNK - 1) cp_wait<0>(); else cp_wait<1>();   // chunk i ready
        __syncthreads();                   // all warps done reading buf (i+2)%3

        if (i + 2 < NCHUNK) {              // prefetch chunk i+2
            int pre = buf + 2; if (pre >= 3) pre -= 3;
            uint32_t dA = sA + pre * bufStride;
            uint32_t dB = sB + pre * bufStride;
            const float* Asrc = Ag + (i + 2) * KC;
            const float* Wsrc = Wg + (i + 2) * KC;
            #pragma unroll
            for (int q = 0; q < 4; q++) {
                cp_async16_ca(dA + q * 16, Asrc + 4 * q);
                cp_async16_ca(dB + q * 16, Wsrc + 4 * q);
            }
            cp_commit();
        }

        const float* Ab   = As + buf * 128 * ASTR;
        const float* Bbuf = Bs + buf * 128 * ASTR;
        #pragma unroll
        for (int kk = 0; kk < KC; kk += 8) {
            uint32_t af[4][4], bf[4][2];
            #pragma unroll
            for (int mt = 0; mt < 4; mt++) {
                int row = mW + mt * 16 + g;
                af[mt][0] = f2tf(Ab[row * ASTR + kk + tg]);
                af[mt][1] = f2tf(Ab[(row + 8) * ASTR + kk + tg]);
                af[mt][2] = f2tf(Ab[row * ASTR + kk + tg + 4]);
                af[mt][3] = f2tf(Ab[(row + 8) * ASTR + kk + tg + 4]);
            }
            #pragma unroll
            for (int nt = 0; nt < 4; nt++) {
                int col = nW + nt * 8 + g;
                bf[nt][0] = f2tf(Bbuf[col * ASTR + kk + tg]);
                bf[nt][1] = f2tf(Bbuf[col * ASTR + kk + tg + 4]);
            }
            #pragma unroll
            for (int mt = 0; mt < 4; mt++)
                #pragma unroll
                for (int nt = 0; nt < 4; nt++)
                    mma_tf32(acc[mt][nt], af[mt][0], af[mt][1], af[mt][2], af[mt][3],
                             bf[nt][0], bf[nt][1]);
        }
        buf = (buf + 1 == 3) ? 0 : buf + 1;
    }

    // epilogue: bias + store
    #pragma unroll
    for (int mt = 0; mt < 4; mt++) {
        int r0 = bm * 128 + mW + mt * 16 + g;
        #pragma unroll
        for (int nt = 0; nt < 4; nt++) {
            int c = bn * 128 + nW + nt * 8 + 2 * tg;
            *(float2*)(g_xproj + (size_t)r0 * GG + c) =
                make_float2(acc[mt][nt][0] + bb[nt][0], acc[mt][nt][1] + bb[nt][1]);
            *(float2*)(g_xproj + (size_t)(r0 + 8) * GG + c) =
                make_float2(acc[mt][nt][2] + bb[nt][0], acc[mt][nt][3] + bb[nt][1]);
        }
    }
}

// ---------------------------------------------------------------------------
// Persistent recurrence kernel (tf32 tensor cores, tree grid barrier).
// 256 blocks = 64 n-tiles x 4 k-splits (K=256 each).
// W tile (64x256, tf32) cached in SMEM for the whole layer.
// h chunks staged raw fp32 via cp.async.cg, tf32 cvt at fragment load.
// ---------------------------------------------------------------------------
#define WSTR 260
#define HSTR 132

__global__ void __launch_bounds__(256, 2) rec_persist_tc_kernel(
    const float* __restrict__ Whh,
    float* __restrict__ out_ext,
    int out_is_hbuf)
{
    extern __shared__ float smf[];
    uint32_t* Ws = (uint32_t*)smf;           // [64][260] tf32 W tile (persistent)
    float*    Hs = smf + 64 * WSTR;          // [64][132] raw fp32 h half-chunk

    const int tid  = threadIdx.x;
    const int bn   = blockIdx.x & 63;
    const int ks   = blockIdx.x >> 6;
    const int kbase = ks * (HH / KSPLIT);

    const int lane = tid & 31, wid = tid >> 5;
    const int g    = lane >> 2, tg = lane & 3;
    const int wm   = wid >> 1;               // 0..3 -> 16 rows
    const int wn   = wid & 1;                // 0..1 -> 32 cols
    const int mW   = wm * 16, nW = wn * 32;

    // Load W tile into SMEM once (tf32-packed)
    {
        int n = tid & 63, cq = tid >> 6;
        const float* Wg = Whh + (size_t)(bn * 64 + n) * HH + kbase;
        for (int q = 0; q < 16; q += 2) {
            int k0 = 4 * (cq + 4 * q);
            int k1 = 4 * (cq + 4 * (q + 1));
            float4 v0 = *(const float4*)(Wg + k0);
            float4 v1 = *(const float4*)(Wg + k1);
            *(uint4*)(Ws + n * WSTR + k0) =
                make_uint4(f2tf(v0.x), f2tf(v0.y), f2tf(v0.z), f2tf(v0.w));
            *(uint4*)(Ws + n * WSTR + k1) =
                make_uint4(f2tf(v1.x), f2tf(v1.y), f2tf(v1.z), f2tf(v1.w));
        }
    }
    __syncthreads();

    // h staging map: row m, col group cq -> 8x 16B cp.async per half
    const int m_st = tid & 63;
    const int cq   = tid >> 6;               // 0..3
    const uint32_t sH = (uint32_t)__cvta_generic_to_shared(Hs + m_st * HSTR);

    // elementwise mapping
    const int eidx = blockIdx.x * 256 + tid;
    const int b = eidx >> 10;
    const int j = eidx & 1023;
    const float* xp_base = g_xproj + (size_t)b * TT * GG + j;
    float* out = out_is_hbuf ? g_hbuf : out_ext;
    float* out_base = out + (size_t)b * TT * HH + j;
    float creg = 0.0f;

    float* Pout = g_part + (size_t)ks * BB * GG + (size_t)bn * 64;

    for (int t = 0; t < TT; t++) {
        if (t > 0) {
            float acc[4][4];
            #pragma unroll
            for (int nt = 0; nt < 4; nt++)
                #pragma unroll
                for (int e = 0; e < 4; e++) acc[nt][e] = 0.f;

            #pragma unroll
            for (int half = 0; half < 2; half++) {
                // stage h chunk [64][128] -> Hs (raw fp32, L2 path)
                {
                    const float* Hg = g_h + (size_t)m_st * HH + kbase + half * 128;
                    #pragma unroll
                    for (int q = 0; q < 8; q++) {
                        int k = 4 * (cq + 4 * q);
                        cp_async16_cg(sH + k * 4, Hg + k);
                    }
                    cp_commit();
                    cp_wait<0>();
                }
                __syncthreads();

                #pragma unroll
                for (int kk = 0; kk < 128; kk += 8) {
                    uint32_t a0 = f2tf(Hs[(mW + g) * HSTR + kk + tg]);
                    uint32_t a1 = f2tf(Hs[(mW + g + 8) * HSTR + kk + tg]);
                    uint32_t a2 = f2tf(Hs[(mW + g) * HSTR + kk + tg + 4]);
                    uint32_t a3 = f2tf(Hs[(mW + g + 8) * HSTR + kk + tg + 4]);
                    #pragma unroll
                    for (int nt = 0; nt < 4; nt++) {
                        int col = nW + nt * 8 + g;
                        uint32_t b0 = Ws[col * WSTR + half * 128 + kk + tg];
                        uint32_t b1 = Ws[col * WSTR + half * 128 + kk + tg + 4];
                        mma_tf32(acc[nt], a0, a1, a2, a3, b0, b1);
                    }
                }
                __syncthreads();
            }

            // write partials
            #pragma unroll
            for (int nt = 0; nt < 4; nt++) {
                int c = nW + nt * 8 + 2 * tg;
                *(float2*)(Pout + (size_t)(mW + g) * GG + c) =
                    make_float2(acc[nt][0], acc[nt][1]);
                *(float2*)(Pout + (size_t)(mW + g + 8) * GG + c) =
                    make_float2(acc[nt][2], acc[nt][3]);
            }
        }

        grid_barrier();   // partials visible

        // phase B: elementwise LSTM update
        {
            const float* xp = xp_base + (size_t)t * GG;
            float gi = xp[0];
            float gf = xp[HH];
            float gg = xp[2 * HH];
            float go = xp[3 * HH];

            if (t > 0) {
                size_t pb = (size_t)b * GG + j;
                #pragma unroll
                for (int s = 0; s < KSPLIT; s++) {
                    const float* P = g_part + (size_t)s * BB * GG + pb;
                    gi += P[0];
                    gf += P[HH];
                    gg += P[2 * HH];
                    go += P[3 * HH];
                }
            }

            float i_g = 1.f / (1.f + expf(-gi));
            float f_g = 1.f / (1.f + expf(-gf));
            float g_g = tanhf(gg);
            float o_g = 1.f / (1.f + expf(-go));

            creg = f_g * creg + i_g * g_g;
            float h = o_g * tanhf(creg);

            g_h[eidx] = h;
            out_base[(size_t)t * HH] = h;
        }

        grid_barrier();   // h visible before next step's GEMM
    }
}

// ---------------------------------------------------------------------------
extern "C" void kernel_launch(void* const* d_in, const int* in_sizes, int n_in,
                              void* d_out, int out_size)
{
    const float* x   = (const float*)d_in[0];   // [B, T, I]
    const float* Wih = (const float*)d_in[1];   // [L, 4H, I]
    const float* Whh = (const float*)d_in[2];   // [L, 4H, H]
    const float* bih = (const float*)d_in[3];   // [L, 4H]
    const float* bhh = (const float*)d_in[4];   // [L, 4H]
    float* out = (float*)d_out;                 // [B, T, H]

    const int gemm_smem = 6 * 128 * ASTR * 4;               // 110592 B (3 bufs x A,B)
    const int rec_smem  = (64 * WSTR + 64 * HSTR) * 4;      // 100352 B
    cudaFuncSetAttribute(gemm_bias_tc_kernel,
                         cudaFuncAttributeMaxDynamicSharedMemorySize, gemm_smem);
    cudaFuncSetAttribute(rec_persist_tc_kernel,
                         cudaFuncAttributeMaxDynamicSharedMemorySize, rec_smem);

    for (int l = 0; l < 3; l++) {
        const float* Wih_l = Wih + (size_t)l * GG * II;
        const float* Whh_l = Whh + (size_t)l * GG * HH;
        const float* bih_l = bih + (size_t)l * GG;
        const float* bhh_l = bhh + (size_t)l * GG;

        int in_is_hbuf  = (l != 0);
        int out_is_hbuf = (l != 2);

        dim3 g1(GG / 128, MM / 128);   // (32, 256)
        gemm_bias_tc_kernel<<<g1, 256, gemm_smem>>>(x, Wih_l, bih_l, bhh_l, in_is_hbuf);

        rec_persist_tc_kernel<<<NBLK, 256, rec_smem>>>(Whh_l, out, out_is_hbuf);
    }
}

// round 10
// speedup vs baseline: 1.5084x; 1.5084x over previous
#include <cuda_runtime.h>
#include <math.h>
#include <stdint.h>

#define BB 64
#define TT 512
#define HH 1024
#define GG 4096              // 4*H
#define KK 2048              // concat K = I + H
#define NBLK 288             // 3 layers x 96 blocks
#define LBLK 96
#define NSTEP (TT + 2)       // 514 pipeline steps
#define WSTRIDE 36

// Scratch (device globals: allocation-free per harness rules)
__device__ uint32_t g_wpack[(size_t)3 * GG * KK];      // tf32 W_cat [l][n][k], 96 MB
__device__ float    g_bias [3 * GG];                   // bih+bhh
__device__ float    g_hstate[3 * BB * HH];             // per-layer h state
__device__ float    g_seq  [2][(size_t)BB * TT * HH];  // inter-layer sequence buffers
__device__ float    g_part [3][3][BB * GG];            // [layer][ksplit][64][4096]

// Flat grid barrier (monotonic, zero-initialized) — proven in R6
__device__ unsigned g_bar_count;
__device__ volatile unsigned g_bar_gen;

__device__ __forceinline__ void grid_barrier()
{
    __syncthreads();
    if (threadIdx.x == 0) {
        unsigned gen = g_bar_gen;
        __threadfence();
        unsigned prev = atomicAdd(&g_bar_count, 1u);
        if (prev == (unsigned)(NBLK - 1)) {
            atomicExch(&g_bar_count, 0u);
            __threadfence();
            g_bar_gen = gen + 1;
        } else {
            while (g_bar_gen == gen) { }
            __threadfence();
        }
    }
    __syncthreads();
}

// ---------------------------------------------------------------------------
// tf32 / cp.async helpers
// ---------------------------------------------------------------------------
__device__ __forceinline__ uint32_t f2tf(float f)
{
    uint32_t u;
    asm("cvt.rna.tf32.f32 %0, %1;" : "=r"(u) : "f"(f));
    return u;
}

__device__ __forceinline__ void mma_tf32(float* d,
    uint32_t a0, uint32_t a1, uint32_t a2, uint32_t a3,
    uint32_t b0, uint32_t b1)
{
    asm("mma.sync.aligned.m16n8k8.row.col.f32.tf32.tf32.f32 "
        "{%0,%1,%2,%3}, {%4,%5,%6,%7}, {%8,%9}, {%0,%1,%2,%3};"
        : "+f"(d[0]), "+f"(d[1]), "+f"(d[2]), "+f"(d[3])
        : "r"(a0), "r"(a1), "r"(a2), "r"(a3), "r"(b0), "r"(b1));
}

__device__ __forceinline__ void cp_async16_cg(uint32_t saddr, const void* g)
{
    asm volatile("cp.async.cg.shared.global [%0], [%1], 16;" :: "r"(saddr), "l"(g));
}
__device__ __forceinline__ void cp_commit() { asm volatile("cp.async.commit_group;"); }
template<int N>
__device__ __forceinline__ void cp_wait() { asm volatile("cp.async.wait_group %0;" :: "n"(N)); }

// ---------------------------------------------------------------------------
// Pack kernel: W_cat -> tf32, bias sum, zero h-state. Runs once per replay.
// idx over 3*4096*512 float4-groups of K.
// ---------------------------------------------------------------------------
__global__ void __launch_bounds__(256) pack_kernel(
    const float* __restrict__ Wih,
    const float* __restrict__ Whh,
    const float* __restrict__ bih,
    const float* __restrict__ bhh)
{
    size_t idx = (size_t)blockIdx.x * 256 + threadIdx.x;
    size_t k4  = idx & 511;          // 0..511 (K/4)
    size_t ln  = idx >> 9;           // l*4096 + n, 0..12287
    int k = (int)(k4 * 4);

    const float* src = (k < 1024)
        ? (Wih + ln * 1024 + k)
        : (Whh + ln * 1024 + (k - 1024));
    float4 v = *(const float4*)src;
    *(uint4*)(g_wpack + ln * KK + k) =
        make_uint4(f2tf(v.x), f2tf(v.y), f2tf(v.z), f2tf(v.w));

    if (idx < 3 * GG)       g_bias[idx]   = bih[idx] + bhh[idx];
    if (idx < 3 * BB * HH)  g_hstate[idx] = 0.f;
}

// ---------------------------------------------------------------------------
// Persistent 3-layer pipelined LSTM kernel.
// Block = (layer, ntile 0..31 of 128 cols, ksplit 0..2 of K=2048).
// Per global step s: layer l runs t = s-l (if 0<=t<512):
//   phase A: partial = A_rows(64 x kchunk) @ Wcat_tile  (tf32 MMA)
//   barrier; phase B: gates = bias + sum partials -> LSTM update; barrier.
// ---------------------------------------------------------------------------
__global__ void __launch_bounds__(256, 2) lstm_pipeline_kernel(
    const float* __restrict__ x, float* __restrict__ out)
{
    extern __shared__ float smf[];
    float* Wb = smf;                          // [2][128*36] tf32 (as float bits)
    float* Ab = smf + 2 * 128 * WSTRIDE;      // [2][64*36] raw fp32

    const int tid   = threadIdx.x;
    const int bid   = blockIdx.x;
    const int layer = bid / LBLK;
    const int rel   = bid % LBLK;
    const int ntile = rel & 31;
    const int ksl   = rel >> 5;
    const int n0    = ntile * 128;
    const int kbeg  = (ksl == 0) ? 0   : (ksl == 1) ? 672  : 1376;
    const int kend  = (ksl == 0) ? 672 : (ksl == 1) ? 1376 : 2048;
    const int nch   = (kend - kbeg) >> 5;     // 21 / 22 / 21 chunks of 32

    const int lane = tid & 31, wid = tid >> 5;
    const int g = lane >> 2, tg = lane & 3;   // warp covers n in [wid*16, wid*16+16)

    // staging maps
    const int wr = tid >> 1, wh = tid & 1;    // W: 128 rows x 2 halves of 16 floats
    const int ar = tid >> 2, aq = tid & 3;    // A: 64 rows x 4 quarters of 8 floats

    const uint32_t sW = (uint32_t)__cvta_generic_to_shared(Wb + wr * WSTRIDE + wh * 16);
    const uint32_t sA = (uint32_t)__cvta_generic_to_shared(Ab + ar * WSTRIDE + aq * 8);
    const uint32_t wBufB = 128 * WSTRIDE * 4;
    const uint32_t aBufB = 64 * WSTRIDE * 4;

    const uint32_t* Wsrc = g_wpack + (size_t)(layer * GG + n0 + wr) * KK + wh * 16;
    const float*  inbase = (layer == 0) ? x : g_seq[layer - 1];
    const float*  hbase  = g_hstate + layer * (BB * HH);
    float* Pout = &g_part[layer][ksl][0];
    const float* bias = g_bias + layer * GG;
    float* seqout = (layer == 2) ? out : g_seq[layer];

    // phase B: threads of this layer's 96 blocks cover 64*1024 elements, up to 3 each
    const int gt = rel * 256 + tid;           // 0..24575
    float creg[3] = {0.f, 0.f, 0.f};

    for (int s = 0; s < NSTEP; s++) {
        const int t = s - layer;
        const bool active = (t >= 0) && (t < TT);

        if (active) {
            // ------------- phase A: tf32 MMA over this block's k-range -------------
            float acc[4][2][4];
            #pragma unroll
            for (int mt = 0; mt < 4; mt++)
                #pragma unroll
                for (int nt = 0; nt < 2; nt++)
                    #pragma unroll
                    for (int e = 0; e < 4; e++) acc[mt][nt][e] = 0.f;

            // prologue: stage chunk 0 into buf 0
            {
                const uint32_t* ws = Wsrc + kbeg;
                cp_async16_cg(sW + 0,  ws + 0);
                cp_async16_cg(sW + 16, ws + 4);
                cp_async16_cg(sW + 32, ws + 8);
                cp_async16_cg(sW + 48, ws + 12);
                const float* as = (kbeg < 1024)
                    ? inbase + ((size_t)ar * TT + t) * HH + kbeg + aq * 8
                    : hbase + (size_t)ar * HH + (kbeg - 1024) + aq * 8;
                cp_async16_cg(sA + 0,  as + 0);
                cp_async16_cg(sA + 16, as + 4);
                cp_commit();
            }

            int buf = 0;
            for (int i = 0; i < nch; i++) {
                if (i + 1 < nch) {
                    int kb = kbeg + (i + 1) * 32;
                    uint32_t dW = sW + (buf ^ 1) * wBufB;
                    const uint32_t* ws = Wsrc + kb;
                    cp_async16_cg(dW + 0,  ws + 0);
                    cp_async16_cg(dW + 16, ws + 4);
                    cp_async16_cg(dW + 32, ws + 8);
                    cp_async16_cg(dW + 48, ws + 12);
                    const float* as = (kb < 1024)
                        ? inbase + ((size_t)ar * TT + t) * HH + kb + aq * 8
                        : hbase + (size_t)ar * HH + (kb - 1024) + aq * 8;
                    uint32_t dA = sA + (buf ^ 1) * aBufB;
                    cp_async16_cg(dA + 0,  as + 0);
                    cp_async16_cg(dA + 16, as + 4);
                    cp_commit();
                    cp_wait<1>();
                } else {
                    cp_wait<0>();
                }
                __syncthreads();

                const uint32_t* Wc = (const uint32_t*)Wb + buf * 128 * WSTRIDE;
                const float*    Ac = Ab + buf * 64 * WSTRIDE;
                #pragma unroll
                for (int kk = 0; kk < 32; kk += 8) {
                    uint32_t a[4][4];
                    #pragma unroll
                    for (int mt = 0; mt < 4; mt++) {
                        int r = mt * 16 + g;
                        a[mt][0] = f2tf(Ac[r * WSTRIDE + kk + tg]);
                        a[mt][1] = f2tf(Ac[(r + 8) * WSTRIDE + kk + tg]);
                        a[mt][2] = f2tf(Ac[r * WSTRIDE + kk + tg + 4]);
                        a[mt][3] = f2tf(Ac[(r + 8) * WSTRIDE + kk + tg + 4]);
                    }
                    uint32_t bf[2][2];
                    #pragma unroll
                    for (int nt = 0; nt < 2; nt++) {
                        int c = wid * 16 + nt * 8 + g;
                        bf[nt][0] = Wc[c * WSTRIDE + kk + tg];
                        bf[nt][1] = Wc[c * WSTRIDE + kk + tg + 4];
                    }
                    #pragma unroll
                    for (int mt = 0; mt < 4; mt++)
                        #pragma unroll
                        for (int nt = 0; nt < 2; nt++)
                            mma_tf32(acc[mt][nt], a[mt][0], a[mt][1], a[mt][2], a[mt][3],
                                     bf[nt][0], bf[nt][1]);
                }
                __syncthreads();
                buf ^= 1;
            }

            // write partials [64][128] -> g_part[layer][ksl]
            #pragma unroll
            for (int mt = 0; mt < 4; mt++) {
                int r = mt * 16 + g;
                #pragma unroll
                for (int nt = 0; nt < 2; nt++) {
                    int c = n0 + wid * 16 + nt * 8 + tg * 2;
                    *(float2*)(Pout + (size_t)r * GG + c) =
                        make_float2(acc[mt][nt][0], acc[mt][nt][1]);
                    *(float2*)(Pout + (size_t)(r + 8) * GG + c) =
                        make_float2(acc[mt][nt][2], acc[mt][nt][3]);
                }
            }
        }

        grid_barrier();   // partials visible

        if (active) {
            // ------------- phase B: elementwise LSTM update -------------
            #pragma unroll
            for (int i = 0; i < 3; i++) {
                int e = gt + i * (LBLK * 256);
                if (e < BB * HH) {
                    int b = e >> 10, j = e & 1023;
                    float gi = bias[j];
                    float gf = bias[j + 1024];
                    float gg = bias[j + 2048];
                    float go = bias[j + 3072];
                    #pragma unroll
                    for (int sp = 0; sp < 3; sp++) {
                        const float* P = &g_part[layer][sp][0] + (size_t)b * GG;
                        gi += P[j];
                        gf += P[j + 1024];
                        gg += P[j + 2048];
                        go += P[j + 3072];
                    }
                    float i_g = 1.f / (1.f + expf(-gi));
                    float f_g = 1.f / (1.f + expf(-gf));
                    float g_g = tanhf(gg);
                    float o_g = 1.f / (1.f + expf(-go));
                    float c = f_g * creg[i] + i_g * g_g;
                    creg[i] = c;
                    float h = o_g * tanhf(c);
                    g_hstate[layer * BB * HH + e] = h;
                    seqout[((size_t)b * TT + t) * HH + j] = h;
                }
            }
        }

        grid_barrier();   // h + seq visible before next step
    }
}

// ---------------------------------------------------------------------------
extern "C" void kernel_launch(void* const* d_in, const int* in_sizes, int n_in,
                              void* d_out, int out_size)
{
    const float* x   = (const float*)d_in[0];   // [B, T, I]
    const float* Wih = (const float*)d_in[1];   // [L, 4H, I]
    const float* Whh = (const float*)d_in[2];   // [L, 4H, H]
    const float* bih = (const float*)d_in[3];   // [L, 4H]
    const float* bhh = (const float*)d_in[4];   // [L, 4H]
    float* out = (float*)d_out;                 // [B, T, H]

    const int smem = (2 * 128 * WSTRIDE + 2 * 64 * WSTRIDE) * 4;  // 55296 B
    cudaFuncSetAttribute(lstm_pipeline_kernel,
                         cudaFuncAttributeMaxDynamicSharedMemorySize, smem);

    pack_kernel<<<3 * GG * (KK / 4) / 256, 256>>>(Wih, Whh, bih, bhh);
    lstm_pipeline_kernel<<<NBLK, 256, smem>>>(x, out);
}

// round 13
// speedup vs baseline: 1.5353x; 1.0179x over previous
#include <cuda_runtime.h>
#include <math.h>
#include <stdint.h>

#define BB 64
#define TT 512
#define HH 1024
#define GG 4096              // 4*H
#define KK 2048              // concat K = I + H
#define NBLK 288             // 3 layers x 96 blocks
#define LBLK 96
#define NSTEP (TT + 2)       // 514 pipeline steps
#define WSTRIDE 36
#define NSTAGE 4

// Scratch (device globals: allocation-free per harness rules)
__device__ uint32_t g_wpack[(size_t)3 * GG * KK];      // tf32 W_cat [l][n][k], 96 MB
__device__ float    g_bias [3 * GG];                   // bih+bhh
__device__ float    g_hstate[3 * BB * HH];             // per-layer h state
__device__ float    g_seq  [2][(size_t)BB * TT * HH];  // inter-layer sequence buffers
__device__ float    g_part [3][3][BB * GG];            // [layer][ksplit][64][4096]

// Flat grid barrier (monotonic, zero-initialized) — proven in R6/R10
__device__ unsigned g_bar_count;
__device__ volatile unsigned g_bar_gen;

__device__ __forceinline__ void grid_barrier()
{
    __syncthreads();
    if (threadIdx.x == 0) {
        unsigned gen = g_bar_gen;
        __threadfence();
        unsigned prev = atomicAdd(&g_bar_count, 1u);
        if (prev == (unsigned)(NBLK - 1)) {
            atomicExch(&g_bar_count, 0u);
            __threadfence();
            g_bar_gen = gen + 1;
        } else {
            while (g_bar_gen == gen) { }
            __threadfence();
        }
    }
    __syncthreads();
}

// ---------------------------------------------------------------------------
// tf32 / cp.async helpers
// ---------------------------------------------------------------------------
__device__ __forceinline__ uint32_t f2tf(float f)
{
    uint32_t u;
    asm("cvt.rna.tf32.f32 %0, %1;" : "=r"(u) : "f"(f));
    return u;
}

__device__ __forceinline__ void mma_tf32(float* d,
    uint32_t a0, uint32_t a1, uint32_t a2, uint32_t a3,
    uint32_t b0, uint32_t b1)
{
    asm("mma.sync.aligned.m16n8k8.row.col.f32.tf32.tf32.f32 "
        "{%0,%1,%2,%3}, {%4,%5,%6,%7}, {%8,%9}, {%0,%1,%2,%3};"
        : "+f"(d[0]), "+f"(d[1]), "+f"(d[2]), "+f"(d[3])
        : "r"(a0), "r"(a1), "r"(a2), "r"(a3), "r"(b0), "r"(b1));
}

__device__ __forceinline__ void cp_async16_cg(uint32_t saddr, const void* g)
{
    asm volatile("cp.async.cg.shared.global [%0], [%1], 16;" :: "r"(saddr), "l"(g));
}
__device__ __forceinline__ void cp_commit() { asm volatile("cp.async.commit_group;"); }
template<int N>
__device__ __forceinline__ void cp_wait() { asm volatile("cp.async.wait_group %0;" :: "n"(N)); }

// ---------------------------------------------------------------------------
// Pack kernel: W_cat -> tf32, bias sum, zero h-state. Runs once per replay.
// ---------------------------------------------------------------------------
__global__ void __launch_bounds__(256) pack_kernel(
    const float* __restrict__ Wih,
    const float* __restrict__ Whh,
    const float* __restrict__ bih,
    const float* __restrict__ bhh)
{
    size_t idx = (size_t)blockIdx.x * 256 + threadIdx.x;
    size_t k4  = idx & 511;          // 0..511 (K/4)
    size_t ln  = idx >> 9;           // l*4096 + n, 0..12287
    int k = (int)(k4 * 4);

    const float* src = (k < 1024)
        ? (Wih + ln * 1024 + k)
        : (Whh + ln * 1024 + (k - 1024));
    float4 v = *(const float4*)src;
    *(uint4*)(g_wpack + ln * KK + k) =
        make_uint4(f2tf(v.x), f2tf(v.y), f2tf(v.z), f2tf(v.w));

    if (idx < 3 * GG)       g_bias[idx]   = bih[idx] + bhh[idx];
    if (idx < 3 * BB * HH)  g_hstate[idx] = 0.f;
}

// ---------------------------------------------------------------------------
// Persistent 3-layer pipelined LSTM kernel.
// Block = (layer, ntile 0..31 of 128 cols, ksplit 0..2 of K=2048).
// 4-stage cp.async ring, one __syncthreads per chunk (plain cp.async.cg only).
// ---------------------------------------------------------------------------
__global__ void __launch_bounds__(256, 2) lstm_pipeline_kernel(
    const float* __restrict__ x, float* __restrict__ out)
{
    extern __shared__ float smf[];
    float* Wb = smf;                                 // [4][128*36]
    float* Ab = smf + NSTAGE * 128 * WSTRIDE;        // [4][64*36]

    const int tid   = threadIdx.x;
    const int bid   = blockIdx.x;
    const int layer = bid / LBLK;
    const int rel   = bid % LBLK;
    const int ntile = rel & 31;
    const int ksl   = rel >> 5;
    const int n0    = ntile * 128;
    const int kbeg  = (ksl == 0) ? 0   : (ksl == 1) ? 672  : 1376;
    const int kend  = (ksl == 0) ? 672 : (ksl == 1) ? 1376 : 2048;
    const int nch   = (kend - kbeg) >> 5;            // 21 / 22 / 21 chunks of 32

    const int lane = tid & 31, wid = tid >> 5;
    const int g = lane >> 2, tg = lane & 3;

    // staging maps
    const int wr = tid >> 1, wh = tid & 1;           // W: 128 rows x 2 halves of 16
    const int ar = tid >> 2, aq = tid & 3;           // A: 64 rows x 4 quarters of 8

    const uint32_t sW = (uint32_t)__cvta_generic_to_shared(Wb + wr * WSTRIDE + wh * 16);
    const uint32_t sA = (uint32_t)__cvta_generic_to_shared(Ab + ar * WSTRIDE + aq * 8);
    const uint32_t wBufB = 128 * WSTRIDE * 4;
    const uint32_t aBufB = 64 * WSTRIDE * 4;

    const uint32_t* Wsrc = g_wpack + (size_t)(layer * GG + n0 + wr) * KK + wh * 16;
    const float*  inbase = (layer == 0) ? x : g_seq[layer - 1];
    const float*  hbase  = g_hstate + layer * (BB * HH);
    float* Pout = &g_part[layer][ksl][0];
    const float* bias = g_bias + layer * GG;
    float* seqout = (layer == 2) ? out : g_seq[layer];

    const int gt = rel * 256 + tid;                  // 0..24575
    float creg[3] = {0.f, 0.f, 0.f};

    for (int s = 0; s < NSTEP; s++) {
        const int t = s - layer;
        const bool active = (t >= 0) && (t < TT);

        if (active) {
            float acc[4][2][4];
            #pragma unroll
            for (int mt = 0; mt < 4; mt++)
                #pragma unroll
                for (int nt = 0; nt < 2; nt++)
                    #pragma unroll
                    for (int e = 0; e < 4; e++) acc[mt][nt][e] = 0.f;

            // prologue: stage chunks 0..2 into bufs 0..2, one group each
            #pragma unroll
            for (int j = 0; j < 3; j++) {
                int kb = kbeg + j * 32;
                uint32_t dW = sW + j * wBufB;
                const uint32_t* ws = Wsrc + kb;
                cp_async16_cg(dW + 0,  ws + 0);
                cp_async16_cg(dW + 16, ws + 4);
                cp_async16_cg(dW + 32, ws + 8);
                cp_async16_cg(dW + 48, ws + 12);
                const float* as = (kb < 1024)
                    ? inbase + ((size_t)ar * TT + t) * HH + kb + aq * 8
                    : hbase + (size_t)ar * HH + (kb - 1024) + aq * 8;
                uint32_t dA = sA + j * aBufB;
                cp_async16_cg(dA + 0,  as + 0);
                cp_async16_cg(dA + 16, as + 4);
                cp_commit();
            }

            for (int i = 0; i < nch; i++) {
                if (i < nch - 2)      cp_wait<2>();
                else if (i == nch-2)  cp_wait<1>();
                else                  cp_wait<0>();
                __syncthreads();      // chunk i staged by all; all done reading buf (i+3)&3

                if (i + 3 < nch) {    // prefetch chunk i+3 into buf (i+3)&3
                    int kb = kbeg + (i + 3) * 32;
                    int pb = (i + 3) & 3;
                    uint32_t dW = sW + pb * wBufB;
                    const uint32_t* ws = Wsrc + kb;
                    cp_async16_cg(dW + 0,  ws + 0);
                    cp_async16_cg(dW + 16, ws + 4);
                    cp_async16_cg(dW + 32, ws + 8);
                    cp_async16_cg(dW + 48, ws + 12);
                    const float* as = (kb < 1024)
                        ? inbase + ((size_t)ar * TT + t) * HH + kb + aq * 8
                        : hbase + (size_t)ar * HH + (kb - 1024) + aq * 8;
                    uint32_t dA = sA + pb * aBufB;
                    cp_async16_cg(dA + 0,  as + 0);
                    cp_async16_cg(dA + 16, as + 4);
                    cp_commit();
                }

                const int buf = i & 3;
                const uint32_t* Wc = (const uint32_t*)Wb + buf * 128 * WSTRIDE;
                const float*    Ac = Ab + buf * 64 * WSTRIDE;
                #pragma unroll
                for (int kk = 0; kk < 32; kk += 8) {
                    uint32_t a[4][4];
                    #pragma unroll
                    for (int mt = 0; mt < 4; mt++) {
                        int r = mt * 16 + g;
                        a[mt][0] = f2tf(Ac[r * WSTRIDE + kk + tg]);
                        a[mt][1] = f2tf(Ac[(r + 8) * WSTRIDE + kk + tg]);
                        a[mt][2] = f2tf(Ac[r * WSTRIDE + kk + tg + 4]);
                        a[mt][3] = f2tf(Ac[(r + 8) * WSTRIDE + kk + tg + 4]);
                    }
                    uint32_t bf[2][2];
                    #pragma unroll
                    for (int nt = 0; nt < 2; nt++) {
                        int c = wid * 16 + nt * 8 + g;
                        bf[nt][0] = Wc[c * WSTRIDE + kk + tg];
                        bf[nt][1] = Wc[c * WSTRIDE + kk + tg + 4];
                    }
                    #pragma unroll
                    for (int mt = 0; mt < 4; mt++)
                        #pragma unroll
                        for (int nt = 0; nt < 2; nt++)
                            mma_tf32(acc[mt][nt], a[mt][0], a[mt][1], a[mt][2], a[mt][3],
                                     bf[nt][0], bf[nt][1]);
                }
            }

            // write partials [64][128] -> g_part[layer][ksl]
            #pragma unroll
            for (int mt = 0; mt < 4; mt++) {
                int r = mt * 16 + g;
                #pragma unroll
                for (int nt = 0; nt < 2; nt++) {
                    int c = n0 + wid * 16 + nt * 8 + tg * 2;
                    *(float2*)(Pout + (size_t)r * GG + c) =
                        make_float2(acc[mt][nt][0], acc[mt][nt][1]);
                    *(float2*)(Pout + (size_t)(r + 8) * GG + c) =
                        make_float2(acc[mt][nt][2], acc[mt][nt][3]);
                }
            }
        }

        grid_barrier();   // partials visible

        if (active) {
            #pragma unroll
            for (int i = 0; i < 3; i++) {
                int e = gt + i * (LBLK * 256);
                if (e < BB * HH) {
                    int b = e >> 10, j = e & 1023;
                    float gi = bias[j];
                    float gf = bias[j + 1024];
                    float gg = bias[j + 2048];
                    float go = bias[j + 3072];
                    #pragma unroll
                    for (int sp = 0; sp < 3; sp++) {
                        const float* P = &g_part[layer][sp][0] + (size_t)b * GG;
                        gi += P[j];
                        gf += P[j + 1024];
                        gg += P[j + 2048];
                        go += P[j + 3072];
                    }
                    float i_g = 1.f / (1.f + expf(-gi));
                    float f_g = 1.f / (1.f + expf(-gf));
                    float g_g = tanhf(gg);
                    float o_g = 1.f / (1.f + expf(-go));
                    float c = f_g * creg[i] + i_g * g_g;
                    creg[i] = c;
                    float h = o_g * tanhf(c);
                    g_hstate[layer * BB * HH + e] = h;
                    seqout[((size_t)b * TT + t) * HH + j] = h;
                }
            }
        }

        grid_barrier();   // h + seq visible before next step
    }
}

// ---------------------------------------------------------------------------
extern "C" void kernel_launch(void* const* d_in, const int* in_sizes, int n_in,
                              void* d_out, int out_size)
{
    const float* x   = (const float*)d_in[0];   // [B, T, I]
    const float* Wih = (const float*)d_in[1];   // [L, 4H, I]
    const float* Whh = (const float*)d_in[2];   // [L, 4H, H]
    const float* bih = (const float*)d_in[3];   // [L, 4H]
    const float* bhh = (const float*)d_in[4];   // [L, 4H]
    float* out = (float*)d_out;                 // [B, T, H]

    const int smem = NSTAGE * (128 * WSTRIDE + 64 * WSTRIDE) * 4;  // 110592 B
    cudaFuncSetAttribute(lstm_pipeline_kernel,
                         cudaFuncAttributeMaxDynamicSharedMemorySize, smem);

    pack_kernel<<<3 * GG * (KK / 4) / 256, 256>>>(Wih, Whh, bih, bhh);
    lstm_pipeline_kernel<<<NBLK, 256, smem>>>(x, out);
}

// round 14
// speedup vs baseline: 1.5920x; 1.0369x over previous
#include <cuda_runtime.h>
#include <cuda_fp16.h>
#include <math.h>
#include <stdint.h>

#define BB 64
#define TT 512
#define HH 1024
#define GG 4096              // 4*H
#define KK 2048              // concat K = I + H
#define NBLK 288             // 3 layers x 96 blocks
#define LBLK 96
#define NSTEP (TT + 2)       // 514 pipeline steps
#define ASTR 36              // A row stride (floats)
#define WSTR2 20             // W row stride (uint32 = half2 units), 16 data + 4 pad
#define NSTAGE 4

// Scratch (device globals: allocation-free per harness rules)
__device__ uint32_t g_wpack[(size_t)3 * GG * (KK / 2)]; // half2-packed W, 48 MB
__device__ float    g_bias [3 * GG];                    // bih+bhh
__device__ float    g_hstate[3 * BB * HH];              // per-layer h state
__device__ float    g_seq  [2][(size_t)BB * TT * HH];   // inter-layer sequence buffers
__device__ float    g_part [3][3][BB * GG];             // [layer][ksplit][64][4096]

// Flat grid barrier (monotonic, zero-initialized) — proven R6/R10/R13
__device__ unsigned g_bar_count;
__device__ volatile unsigned g_bar_gen;

__device__ __forceinline__ void grid_barrier()
{
    __syncthreads();
    if (threadIdx.x == 0) {
        unsigned gen = g_bar_gen;
        __threadfence();
        unsigned prev = atomicAdd(&g_bar_count, 1u);
        if (prev == (unsigned)(NBLK - 1)) {
            atomicExch(&g_bar_count, 0u);
            __threadfence();
            g_bar_gen = gen + 1;
        } else {
            while (g_bar_gen == gen) { }
            __threadfence();
        }
    }
    __syncthreads();
}

// ---------------------------------------------------------------------------
// fp16 MMA / cp.async helpers
// ---------------------------------------------------------------------------
__device__ __forceinline__ uint32_t pack_h2(float lo, float hi)
{
    __half2 h = __floats2half2_rn(lo, hi);
    return *(uint32_t*)&h;
}

__device__ __forceinline__ void mma_f16(float* d,
    uint32_t a0, uint32_t a1, uint32_t a2, uint32_t a3,
    uint32_t b0, uint32_t b1)
{
    asm("mma.sync.aligned.m16n8k16.row.col.f32.f16.f16.f32 "
        "{%0,%1,%2,%3}, {%4,%5,%6,%7}, {%8,%9}, {%0,%1,%2,%3};"
        : "+f"(d[0]), "+f"(d[1]), "+f"(d[2]), "+f"(d[3])
        : "r"(a0), "r"(a1), "r"(a2), "r"(a3), "r"(b0), "r"(b1));
}

__device__ __forceinline__ void cp_async16_cg(uint32_t saddr, const void* g)
{
    asm volatile("cp.async.cg.shared.global [%0], [%1], 16;" :: "r"(saddr), "l"(g));
}
__device__ __forceinline__ void cp_commit() { asm volatile("cp.async.commit_group;"); }
template<int N>
__device__ __forceinline__ void cp_wait() { asm volatile("cp.async.wait_group %0;" :: "n"(N)); }

// ---------------------------------------------------------------------------
// Pack kernel: W_cat -> half2 (packed along k), bias sum, zero h-state.
// ---------------------------------------------------------------------------
__global__ void __launch_bounds__(256) pack_kernel(
    const float* __restrict__ Wih,
    const float* __restrict__ Whh,
    const float* __restrict__ bih,
    const float* __restrict__ bhh)
{
    size_t idx = (size_t)blockIdx.x * 256 + threadIdx.x;
    size_t k4  = idx & 511;          // 0..511 (K/4 groups)
    size_t ln  = idx >> 9;           // l*4096 + n, 0..12287
    int k = (int)(k4 * 4);

    const float* src = (k < 1024)
        ? (Wih + ln * 1024 + k)
        : (Whh + ln * 1024 + (k - 1024));
    float4 v = *(const float4*)src;
    uint2 u;
    u.x = pack_h2(v.x, v.y);
    u.y = pack_h2(v.z, v.w);
    *(uint2*)(g_wpack + ln * (KK / 2) + k / 2) = u;

    if (idx < 3 * GG)       g_bias[idx]   = bih[idx] + bhh[idx];
    if (idx < 3 * BB * HH)  g_hstate[idx] = 0.f;
}

// ---------------------------------------------------------------------------
// Persistent 3-layer pipelined LSTM kernel (fp16 MMA, fp32 accumulate).
// Block = (layer, ntile 0..31 of 128 cols, ksplit 0..2 of K=2048).
// 4-stage cp.async ring, one __syncthreads per chunk of k=32.
// W in SMEM as half2 rows (16 uint32 + 4 pad). A staged fp32, packed to
// half2 at fragment build.
// ---------------------------------------------------------------------------
__global__ void __launch_bounds__(256, 2) lstm_pipeline_kernel(
    const float* __restrict__ x, float* __restrict__ out)
{
    extern __shared__ float smf[];
    float* Wb = smf;                                  // [4][128*20] uint32 data
    float* Ab = smf + NSTAGE * 128 * WSTR2;           // [4][64*36] fp32

    const int tid   = threadIdx.x;
    const int bid   = blockIdx.x;
    const int layer = bid / LBLK;
    const int rel   = bid % LBLK;
    const int ntile = rel & 31;
    const int ksl   = rel >> 5;
    const int n0    = ntile * 128;
    const int kbeg  = (ksl == 0) ? 0   : (ksl == 1) ? 672  : 1376;
    const int kend  = (ksl == 0) ? 672 : (ksl == 1) ? 1376 : 2048;
    const int nch   = (kend - kbeg) >> 5;             // 21 / 22 / 21 chunks of 32

    const int lane = tid & 31, wid = tid >> 5;
    const int g = lane >> 2, tg = lane & 3;

    // staging maps
    const int wr = tid >> 1, wh = tid & 1;            // W: 128 rows x 2 halves (8 uint32)
    const int ar = tid >> 2, aq = tid & 3;            // A: 64 rows x 4 quarters of 8 floats

    const uint32_t sW = (uint32_t)__cvta_generic_to_shared(
        (uint32_t*)Wb + wr * WSTR2 + wh * 8);
    const uint32_t sA = (uint32_t)__cvta_generic_to_shared(Ab + ar * ASTR + aq * 8);
    const uint32_t wBufB = 128 * WSTR2 * 4;
    const uint32_t aBufB = 64 * ASTR * 4;

    // per-thread W source: row (n0+wr), half wh (8 uint32 = 16 k-values)
    const uint32_t* Wsrc = g_wpack + (size_t)(layer * GG + n0 + wr) * (KK / 2) + wh * 8;
    const float*  inbase = (layer == 0) ? x : g_seq[layer - 1];
    const float*  hbase  = g_hstate + layer * (BB * HH);
    float* Pout = &g_part[layer][ksl][0];
    const float* bias = g_bias + layer * GG;
    float* seqout = (layer == 2) ? out : g_seq[layer];

    const int gt = rel * 256 + tid;                   // 0..24575
    float creg[3] = {0.f, 0.f, 0.f};

    for (int s = 0; s < NSTEP; s++) {
        const int t = s - layer;
        const bool active = (t >= 0) && (t < TT);

        if (active) {
            float acc[4][2][4];
            #pragma unroll
            for (int mt = 0; mt < 4; mt++)
                #pragma unroll
                for (int nt = 0; nt < 2; nt++)
                    #pragma unroll
                    for (int e = 0; e < 4; e++) acc[mt][nt][e] = 0.f;

            // prologue: stage chunks 0..2 into bufs 0..2, one group each
            #pragma unroll
            for (int j = 0; j < 3; j++) {
                int kb = kbeg + j * 32;
                uint32_t dW = sW + j * wBufB;
                const uint32_t* ws = Wsrc + (kb >> 1);
                cp_async16_cg(dW + 0,  ws + 0);
                cp_async16_cg(dW + 16, ws + 4);
                const float* as = (kb < 1024)
                    ? inbase + ((size_t)ar * TT + t) * HH + kb + aq * 8
                    : hbase + (size_t)ar * HH + (kb - 1024) + aq * 8;
                uint32_t dA = sA + j * aBufB;
                cp_async16_cg(dA + 0,  as + 0);
                cp_async16_cg(dA + 16, as + 4);
                cp_commit();
            }

            for (int i = 0; i < nch; i++) {
                if (i < nch - 2)      cp_wait<2>();
                else if (i == nch-2)  cp_wait<1>();
                else                  cp_wait<0>();
                __syncthreads();      // chunk i staged; all done reading buf (i+3)&3

                if (i + 3 < nch) {    // prefetch chunk i+3 into buf (i+3)&3
                    int kb = kbeg + (i + 3) * 32;
                    int pb = (i + 3) & 3;
                    uint32_t dW = sW + pb * wBufB;
                    const uint32_t* ws = Wsrc + (kb >> 1);
                    cp_async16_cg(dW + 0,  ws + 0);
                    cp_async16_cg(dW + 16, ws + 4);
                    const float* as = (kb < 1024)
                        ? inbase + ((size_t)ar * TT + t) * HH + kb + aq * 8
                        : hbase + (size_t)ar * HH + (kb - 1024) + aq * 8;
                    uint32_t dA = sA + pb * aBufB;
                    cp_async16_cg(dA + 0,  as + 0);
                    cp_async16_cg(dA + 16, as + 4);
                    cp_commit();
                }

                const int buf = i & 3;
                const uint32_t* Wc = (const uint32_t*)Wb + buf * 128 * WSTR2;
                const float*    Ac = Ab + buf * 64 * ASTR;
                #pragma unroll
                for (int kk = 0; kk < 32; kk += 16) {        // two k16 steps
                    const int kk2 = kk >> 1;                 // uint32 offset in W row
                    uint32_t a[4][4];
                    #pragma unroll
                    for (int mt = 0; mt < 4; mt++) {
                        int r = mt * 16 + g;
                        float2 p0 = *(const float2*)(Ac + r * ASTR + kk + 2 * tg);
                        float2 p1 = *(const float2*)(Ac + (r + 8) * ASTR + kk + 2 * tg);
                        float2 p2 = *(const float2*)(Ac + r * ASTR + kk + 2 * tg + 8);
                        float2 p3 = *(const float2*)(Ac + (r + 8) * ASTR + kk + 2 * tg + 8);
                        a[mt][0] = pack_h2(p0.x, p0.y);
                        a[mt][1] = pack_h2(p1.x, p1.y);
                        a[mt][2] = pack_h2(p2.x, p2.y);
                        a[mt][3] = pack_h2(p3.x, p3.y);
                    }
                    uint32_t bf[2][2];
                    #pragma unroll
                    for (int nt = 0; nt < 2; nt++) {
                        int c = wid * 16 + nt * 8 + g;
                        bf[nt][0] = Wc[c * WSTR2 + kk2 + tg];
                        bf[nt][1] = Wc[c * WSTR2 + kk2 + tg + 4];
                    }
                    #pragma unroll
                    for (int mt = 0; mt < 4; mt++)
                        #pragma unroll
                        for (int nt = 0; nt < 2; nt++)
                            mma_f16(acc[mt][nt], a[mt][0], a[mt][1], a[mt][2], a[mt][3],
                                    bf[nt][0], bf[nt][1]);
                }
            }

            // write partials [64][128] -> g_part[layer][ksl]
            #pragma unroll
            for (int mt = 0; mt < 4; mt++) {
                int r = mt * 16 + g;
                #pragma unroll
                for (int nt = 0; nt < 2; nt++) {
                    int c = n0 + wid * 16 + nt * 8 + tg * 2;
                    *(float2*)(Pout + (size_t)r * GG + c) =
                        make_float2(acc[mt][nt][0], acc[mt][nt][1]);
                    *(float2*)(Pout + (size_t)(r + 8) * GG + c) =
                        make_float2(acc[mt][nt][2], acc[mt][nt][3]);
                }
            }
        }

        grid_barrier();   // partials visible

        if (active) {
            #pragma unroll
            for (int i = 0; i < 3; i++) {
                int e = gt + i * (LBLK * 256);
                if (e < BB * HH) {
                    int b = e >> 10, j = e & 1023;
                    float gi = bias[j];
                    float gf = bias[j + 1024];
                    float gg = bias[j + 2048];
                    float go = bias[j + 3072];
                    #pragma unroll
                    for (int sp = 0; sp < 3; sp++) {
                        const float* P = &g_part[layer][sp][0] + (size_t)b * GG;
                        gi += P[j];
                        gf += P[j + 1024];
                        gg += P[j + 2048];
                        go += P[j + 3072];
                    }
                    float i_g = 1.f / (1.f + expf(-gi));
                    float f_g = 1.f / (1.f + expf(-gf));
                    float g_g = tanhf(gg);
                    float o_g = 1.f / (1.f + expf(-go));
                    float c = f_g * creg[i] + i_g * g_g;
                    creg[i] = c;
                    float h = o_g * tanhf(c);
                    g_hstate[layer * BB * HH + e] = h;
                    seqout[((size_t)b * TT + t) * HH + j] = h;
                }
            }
        }

        grid_barrier();   // h + seq visible before next step
    }
}

// ---------------------------------------------------------------------------
extern "C" void kernel_launch(void* const* d_in, const int* in_sizes, int n_in,
                              void* d_out, int out_size)
{
    const float* x   = (const float*)d_in[0];   // [B, T, I]
    const float* Wih = (const float*)d_in[1];   // [L, 4H, I]
    const float* Whh = (const float*)d_in[2];   // [L, 4H, H]
    const float* bih = (const float*)d_in[3];   // [L, 4H]
    const float* bhh = (const float*)d_in[4];   // [L, 4H]
    float* out = (float*)d_out;                 // [B, T, H]

    const int smem = NSTAGE * (128 * WSTR2 + 64 * ASTR) * 4;  // 77824 B
    cudaFuncSetAttribute(lstm_pipeline_kernel,
                         cudaFuncAttributeMaxDynamicSharedMemorySize, smem);

    pack_kernel<<<3 * GG * (KK / 4) / 256, 256>>>(Wih, Whh, bih, bhh);
    lstm_pipeline_kernel<<<NBLK, 256, smem>>>(x, out);
}